// round 12
// baseline (speedup 1.0000x reference)
#include <cuda_runtime.h>
#include <cuda_fp16.h>
#include <cstdint>
#include <math.h>

#define B_  2
#define S_  2048
#define E_  2048
#define H_  16
#define D_  128
#define E3_ 6144

// ---------------- scratch ----------------
__device__ __half g_xh [B_ * S_ * E_];       // x, fp16, K-pair-interleaved
__device__ __half g_wqkvT[E3_ * E_];         // Wqkv^T fp16 interleaved
__device__ __half g_woT [E_ * E_];           // Wo^T fp16 interleaved
__device__ __half g_qh[B_ * H_ * S_ * D_];   // Q fp16 d-interleaved, scaled
__device__ __half g_kh[B_ * H_ * S_ * D_];   // K fp16 d-interleaved
__device__ __half g_vh[B_ * H_ * S_ * D_];   // V fp16 natural
__device__ __half g_aoh[B_ * S_ * E_];       // attn out fp16 interleaved

// ---------------- helpers ----------------
__device__ __forceinline__ uint32_t smem_u32(const void* p) {
    uint32_t a;
    asm("{ .reg .u64 t; cvta.to.shared.u64 t, %1; cvt.u32.u64 %0, t; }" : "=r"(a) : "l"(p));
    return a;
}

#define CP_ASYNC16(sa, gp) \
    asm volatile("cp.async.cg.shared.global [%0], [%1], 16;" :: "r"(sa), "l"(gp))
#define CP_COMMIT() asm volatile("cp.async.commit_group;" ::: "memory")
#define CP_WAIT1()  asm volatile("cp.async.wait_group 1;" ::: "memory")
#define CP_WAIT2()  asm volatile("cp.async.wait_group 2;" ::: "memory")
#define CP_WAIT0()  asm volatile("cp.async.wait_group 0;" ::: "memory")

__device__ __forceinline__ void mma_f16_16n8k16(
    float& c0, float& c1, float& c2, float& c3,
    uint32_t a0, uint32_t a1, uint32_t a2, uint32_t a3,
    uint32_t b0, uint32_t b1)
{
    asm volatile(
        "mma.sync.aligned.m16n8k16.row.col.f32.f16.f16.f32 "
        "{%0,%1,%2,%3}, {%4,%5,%6,%7}, {%8,%9}, {%0,%1,%2,%3};"
        : "+f"(c0), "+f"(c1), "+f"(c2), "+f"(c3)
        : "r"(a0), "r"(a1), "r"(a2), "r"(a3), "r"(b0), "r"(b1));
}

// pair-interleave position within each 16-half block
__device__ __forceinline__ int ilv16(int t) {
    int p = (t >> 1) & 7;
    int np = ((p & 3) << 1) | ((p >> 2) & 1);
    return (t & ~15) | (np << 1) | (t & 1);
}

// ============================================================================
// fp16 mma.sync GEMM with fused epilogue (validated R10, unchanged).
// ============================================================================
#define GSZ 8192
#define GEMM_SMEM (3 * 2 * GSZ * 2)

__global__ __launch_bounds__(256, 2) void gemm_mma(
    const __half* __restrict__ A, const __half* __restrict__ Bt,
    float* __restrict__ C, const float* __restrict__ fc,
    __half* __restrict__ Qo, __half* __restrict__ Ko, __half* __restrict__ Vo,
    int M, int Ntot, int K, int mode)
{
    extern __shared__ __half smh[];
    const int tid  = threadIdx.x;
    const int wid  = tid >> 5;
    const int lane = tid & 31;
    const int gid  = lane >> 2;
    const int tig  = lane & 3;
    const int wm   = wid & 1;
    const int wn   = wid >> 1;
    const int m0 = blockIdx.y * 128;
    const int n0 = blockIdx.x * 128;

    const int r_ld = tid >> 3;
    const int c_ld = tid & 7;
    const int c_sw = c_ld ^ ((r_ld & 3) << 1);
    const int x = (gid & 3) << 1;

    float c[4][4][4];
#pragma unroll
    for (int i = 0; i < 4; ++i)
#pragma unroll
        for (int j = 0; j < 4; ++j)
#pragma unroll
            for (int t = 0; t < 4; ++t) c[i][j][t] = 0.f;

    auto load_stage = [&](int kc, int slot) {
        __half* As = smh + slot * 2 * GSZ;
        __half* Bs = As + GSZ;
        const __half* Ag = A + (size_t)m0 * K + kc * 64;
        const __half* Bg = Bt + (size_t)n0 * K + kc * 64;
#pragma unroll
        for (int j = 0; j < 4; ++j) {
            int r = r_ld + j * 32;
            CP_ASYNC16(smem_u32(As + r * 64 + c_sw * 8), Ag + (size_t)r * K + c_ld * 8);
        }
#pragma unroll
        for (int j = 0; j < 4; ++j) {
            int r = r_ld + j * 32;
            CP_ASYNC16(smem_u32(Bs + r * 64 + c_sw * 8), Bg + (size_t)r * K + c_ld * 8);
        }
    };

    const int nk = K >> 6;
    load_stage(0, 0); CP_COMMIT();
    load_stage(1, 1); CP_COMMIT();

    for (int kc = 0; kc < nk; ++kc) {
        CP_WAIT1();
        __syncthreads();
        if (kc + 2 < nk) { load_stage(kc + 2, (kc + 2) % 3); CP_COMMIT(); }

        const __half* As = smh + (kc % 3) * 2 * GSZ;
        const __half* Bs = As + GSZ;
        const __half* Aw = As + (wm * 64 + gid) * 64;
        const __half* Bw = Bs + (wn * 32 + gid) * 64;

#pragma unroll
        for (int ks = 0; ks < 4; ++ks) {
            const int swc = (2 * ks + (tig >> 1)) ^ x;
            const int off = swc * 8 + (tig & 1) * 4;
            uint32_t a[4][4], b[4][2];
#pragma unroll
            for (int mt = 0; mt < 4; ++mt) {
                uint2 p0 = *(const uint2*)(Aw + mt * 1024 + off);
                uint2 p1 = *(const uint2*)(Aw + mt * 1024 + 512 + off);
                a[mt][0] = p0.x;  a[mt][2] = p0.y;
                a[mt][1] = p1.x;  a[mt][3] = p1.y;
            }
#pragma unroll
            for (int nt = 0; nt < 4; ++nt) {
                uint2 pb = *(const uint2*)(Bw + nt * 512 + off);
                b[nt][0] = pb.x;  b[nt][1] = pb.y;
            }
#pragma unroll
            for (int mt = 0; mt < 4; ++mt)
#pragma unroll
                for (int nt = 0; nt < 4; ++nt)
                    mma_f16_16n8k16(c[mt][nt][0], c[mt][nt][1], c[mt][nt][2], c[mt][nt][3],
                                    a[mt][0], a[mt][1], a[mt][2], a[mt][3],
                                    b[nt][0], b[nt][1]);
        }
    }

    if (mode == 0) {
#pragma unroll
        for (int mt = 0; mt < 4; ++mt) {
            int r0 = m0 + wm * 64 + mt * 16 + gid;
#pragma unroll
            for (int nt = 0; nt < 4; ++nt) {
                int col = n0 + wn * 32 + nt * 8 + 2 * tig;
                *(float2*)(C + (size_t)r0 * Ntot + col) = make_float2(c[mt][nt][0], c[mt][nt][1]);
                *(float2*)(C + (size_t)(r0 + 8) * Ntot + col) = make_float2(c[mt][nt][2], c[mt][nt][3]);
            }
        }
    } else {
        const int region = n0 >> 11;
        const int h = (n0 & 2047) >> 7;
        const float sc = 0.08838834764831845f;
#pragma unroll
        for (int mt = 0; mt < 4; ++mt) {
            int r0 = m0 + wm * 64 + mt * 16 + gid;
#pragma unroll
            for (int half_row = 0; half_row < 2; ++half_row) {
                int row = r0 + half_row * 8;
                int s = row & 2047, b = row >> 11;
                size_t bo = ((size_t)(b * H_ + h) * S_ + s) * (size_t)D_;
#pragma unroll
                for (int nt = 0; nt < 4; ++nt) {
                    float v0 = c[mt][nt][half_row * 2 + 0];
                    float v1 = c[mt][nt][half_row * 2 + 1];
                    int i = wn * 16 + nt * 4 + tig;
                    if (region < 2) {
                        float co = fc[s * 128 + 2 * i];
                        float sn = fc[s * 128 + 2 * i + 1];
                        float re = v0 * co - v1 * sn;
                        float im = v1 * co + v0 * sn;
                        if (region == 0) { re *= sc; im *= sc; }
                        int p = i & 7;
                        int np = ((p & 3) << 1) | ((p >> 2) & 1);
                        int pos = (i >> 3) * 16 + np * 2;
                        __half2 hv = __floats2half2_rn(re, im);
                        if (region == 0) *(__half2*)(Qo + bo + pos) = hv;
                        else             *(__half2*)(Ko + bo + pos) = hv;
                    } else {
                        *(__half2*)(Vo + bo + 2 * i) = __floats2half2_rn(v0, v1);
                    }
                }
            }
        }
    }
}

// ============================================================================
// prep kernels (validated)
// ============================================================================
__global__ __launch_bounds__(256) void round_copy_h(const float* __restrict__ in,
                                                    __half* __restrict__ out) {
    int i = blockIdx.x * 256 + threadIdx.x;
    const float* p = in + 16 * i;
    __half2 h[8];
#pragma unroll
    for (int j = 0; j < 8; ++j) {
        int pp = (j >> 1) | ((j & 1) << 2);
        h[j] = __floats2half2_rn(p[2 * pp], p[2 * pp + 1]);
    }
    uint4* q = (uint4*)(out + 16 * i);
    q[0] = *(uint4*)(h);
    q[1] = *(uint4*)(h + 4);
}

__global__ __launch_bounds__(256) void transpose_round_h(
    const float* __restrict__ W, __half* __restrict__ Wt, int K, int N)
{
    __shared__ float t[32][33];
    int n0 = blockIdx.x * 32, k0 = blockIdx.y * 32;
    int tx = threadIdx.x & 31, ty = threadIdx.x >> 5;
#pragma unroll
    for (int j = 0; j < 4; ++j)
        t[ty + j * 8][tx] = W[(size_t)(k0 + ty + j * 8) * N + n0 + tx];
    __syncthreads();
    int ktx = ilv16(tx);
#pragma unroll
    for (int j = 0; j < 4; ++j)
        Wt[(size_t)(n0 + ty + j * 8) * K + k0 + ktx] = __float2half(t[tx][ty + j * 8]);
}

// ============================================================================
// Flash attention v3: R10 structure (BM=128, BN=64, 256 threads, 8 warps)
// + 2 CTAs/SM (cross-CTA overlap hides softmax/barrier bubbles)
// + Q fragments re-loaded via LDG each iter (L1-resident; frees 32 regs)
// + correct cp.async grouping (K and V each own group, wait_group 2).
// ============================================================================
#define KSP 136
#define VSP 72
#define PSP 72
#define KS_H (64 * KSP)
#define VTS_H (128 * VSP)
#define PS_H (128 * PSP)
#define FL_SMEM ((2 * KS_H + 2 * VTS_H + PS_H) * 2)   // 90112 B -> 2 CTAs/SM

__global__ __launch_bounds__(256, 2) void flash_mma(
    const __half* __restrict__ Qg, const __half* __restrict__ Kg,
    const __half* __restrict__ Vg, __half* __restrict__ Og)
{
    extern __shared__ __half smh[];
    __half* Ks  = smh;                 // [2][64][KSP]
    __half* Vts = smh + 2 * KS_H;      // [2][128(d)][VSP(key)]
    __half* Ps  = Vts + 2 * VTS_H;     // [128][PSP]

    const int tid  = threadIdx.x;
    const int wid  = tid >> 5;
    const int lane = tid & 31;
    const int gid  = lane >> 2;
    const int tig  = lane & 3;
    const int b = blockIdx.z, h = blockIdx.y;
    const int qt = (int)gridDim.x - 1 - (int)blockIdx.x;  // big tiles first
    const int q0 = qt * 128;
    const int wrow = wid * 16;
    const size_t base = (size_t)(b * H_ + h) * S_ * D_;

    // Q fragment pointers (LDG each iter; L1-resident after first tile)
    const __half* Qp0 = Qg + base + (size_t)(q0 + wrow + gid) * D_ + tig * 4;
    const __half* Qp1 = Qp0 + 8 * D_;

    float accO[16][4];
#pragma unroll
    for (int nt = 0; nt < 16; ++nt)
#pragma unroll
        for (int t = 0; t < 4; ++t) accO[nt][t] = 0.f;
    float mrow0 = -3.0e38f, mrow1 = -3.0e38f;
    float lrow0 = 0.f, lrow1 = 0.f;

    auto load_K = [&](int kt, int bf) {
        const __half* Kgp = Kg + base + (size_t)kt * 64 * D_;
        __half* dst = Ks + bf * KS_H;
#pragma unroll
        for (int j = 0; j < 4; ++j) {
            int q = tid + j * 256;
            int r = q >> 4, cc = q & 15;
            CP_ASYNC16(smem_u32(dst + r * KSP + cc * 8), Kgp + (size_t)r * D_ + cc * 8);
        }
    };
    auto load_V = [&](int kt, int bf) {
        const __half* Vgp = Vg + base + (size_t)kt * 64 * D_;
        __half* dst = Vts + bf * VTS_H;
#pragma unroll
        for (int j = 0; j < 8; ++j) {
            int e = tid + j * 256;
            int key = e & 63, d4 = e >> 6;
            uint2 v4 = *(const uint2*)(Vgp + (size_t)key * D_ + d4 * 4);
            __half2 lo = *(__half2*)&v4.x;
            __half2 hi = *(__half2*)&v4.y;
            int ik = ilv16(key);
            dst[(d4 * 4 + 0) * VSP + ik] = __low2half(lo);
            dst[(d4 * 4 + 1) * VSP + ik] = __high2half(lo);
            dst[(d4 * 4 + 2) * VSP + ik] = __low2half(hi);
            dst[(d4 * 4 + 3) * VSP + ik] = __high2half(hi);
        }
    };

    const int nkt = 2 * qt + 1;
    load_K(0, 0); CP_COMMIT();           // group: K0
    load_V(0, 0); CP_COMMIT();           // group: V0

    const int row0s = (wrow + gid) * PSP;
    const int row1s = row0s + 8 * PSP;

    for (int kt = 0; kt <= nkt; ++kt) {
        const int cur = kt & 1, nxt = cur ^ 1;
        if (kt < nkt) { load_K(kt + 1, nxt); CP_COMMIT(); CP_WAIT2(); }
        else          { CP_WAIT0(); }
        __syncthreads();    // K[cur] visible in all threads; Ps free

        // ---- S = Q @ K^T ----
        float sacc[8][4];
#pragma unroll
        for (int nt = 0; nt < 8; ++nt)
#pragma unroll
            for (int t = 0; t < 4; ++t) sacc[nt][t] = 0.f;

        const __half* Kb = Ks + cur * KS_H + gid * KSP + tig * 4;
#pragma unroll
        for (int ks = 0; ks < 8; ++ks) {
            uint2 qa0 = *(const uint2*)(Qp0 + ks * 16);
            uint2 qa1 = *(const uint2*)(Qp1 + ks * 16);
#pragma unroll
            for (int nt = 0; nt < 8; ++nt) {
                uint2 bb = *(const uint2*)(Kb + nt * 8 * KSP + ks * 16);
                mma_f16_16n8k16(sacc[nt][0], sacc[nt][1], sacc[nt][2], sacc[nt][3],
                                qa0.x, qa1.x, qa0.y, qa1.y, bb.x, bb.y);
            }
        }

        if (kt < nkt) { load_V(kt + 1, nxt); CP_COMMIT(); CP_WAIT2(); }
        else          { CP_WAIT0(); }   // V[cur] arrived (all threads, via barrier below)

        // ---- causal mask ----
        const int k0 = kt * 64;
        if (k0 + 63 > q0 + wrow) {
            int r0 = q0 + wrow + gid, r1 = r0 + 8;
#pragma unroll
            for (int nt = 0; nt < 8; ++nt) {
                int cA = k0 + nt * 8 + 2 * tig, cB = cA + 1;
                if (cA > r0) sacc[nt][0] = -1.0e30f;
                if (cB > r0) sacc[nt][1] = -1.0e30f;
                if (cA > r1) sacc[nt][2] = -1.0e30f;
                if (cB > r1) sacc[nt][3] = -1.0e30f;
            }
        }

        // ---- online softmax (2 rows/thread, 4-lane groups) ----
        float mx0 = -3.0e38f, mx1 = -3.0e38f;
#pragma unroll
        for (int nt = 0; nt < 8; ++nt) {
            mx0 = fmaxf(mx0, fmaxf(sacc[nt][0], sacc[nt][1]));
            mx1 = fmaxf(mx1, fmaxf(sacc[nt][2], sacc[nt][3]));
        }
        mx0 = fmaxf(mx0, __shfl_xor_sync(0xffffffffu, mx0, 1));
        mx0 = fmaxf(mx0, __shfl_xor_sync(0xffffffffu, mx0, 2));
        mx1 = fmaxf(mx1, __shfl_xor_sync(0xffffffffu, mx1, 1));
        mx1 = fmaxf(mx1, __shfl_xor_sync(0xffffffffu, mx1, 2));

        float mn0 = fmaxf(mrow0, mx0);
        float mn1 = fmaxf(mrow1, mx1);
        float al0 = __expf(mrow0 - mn0);
        float al1 = __expf(mrow1 - mn1);
        mrow0 = mn0; mrow1 = mn1;

        float s0 = 0.f, s1 = 0.f;
#pragma unroll
        for (int nt = 0; nt < 8; ++nt) {
            sacc[nt][0] = __expf(sacc[nt][0] - mn0);
            sacc[nt][1] = __expf(sacc[nt][1] - mn0);
            sacc[nt][2] = __expf(sacc[nt][2] - mn1);
            sacc[nt][3] = __expf(sacc[nt][3] - mn1);
            s0 += sacc[nt][0] + sacc[nt][1];
            s1 += sacc[nt][2] + sacc[nt][3];
        }
        s0 += __shfl_xor_sync(0xffffffffu, s0, 1);
        s0 += __shfl_xor_sync(0xffffffffu, s0, 2);
        s1 += __shfl_xor_sync(0xffffffffu, s1, 1);
        s1 += __shfl_xor_sync(0xffffffffu, s1, 2);
        lrow0 = lrow0 * al0 + s0;
        lrow1 = lrow1 * al1 + s1;

#pragma unroll
        for (int nt = 0; nt < 16; ++nt) {
            accO[nt][0] *= al0; accO[nt][1] *= al0;
            accO[nt][2] *= al1; accO[nt][3] *= al1;
        }
        // ---- P -> smem fp16 (key-pair-interleaved, 16-half blocks) ----
#pragma unroll
        for (int nt = 0; nt < 8; ++nt) {
            int np = 2 * tig + (nt & 1);
            int off = (nt >> 1) * 16 + np * 2;
            *(__half2*)(Ps + row0s + off) = __floats2half2_rn(sacc[nt][0], sacc[nt][1]);
            *(__half2*)(Ps + row1s + off) = __floats2half2_rn(sacc[nt][2], sacc[nt][3]);
        }
        __syncthreads();    // P visible; V[cur] visible (every thread waited above)

        // ---- O += P @ V ----
        const __half* Vb = Vts + cur * VTS_H + gid * VSP + tig * 4;
        const __half* Pb0 = Ps + row0s + tig * 4;
        const __half* Pb1 = Ps + row1s + tig * 4;
#pragma unroll
        for (int ks2 = 0; ks2 < 4; ++ks2) {
            uint2 pa0 = *(const uint2*)(Pb0 + ks2 * 16);
            uint2 pa1 = *(const uint2*)(Pb1 + ks2 * 16);
#pragma unroll
            for (int nt = 0; nt < 16; ++nt) {
                uint2 vb = *(const uint2*)(Vb + nt * 8 * VSP + ks2 * 16);
                mma_f16_16n8k16(accO[nt][0], accO[nt][1], accO[nt][2], accO[nt][3],
                                pa0.x, pa1.x, pa0.y, pa1.y, vb.x, vb.y);
            }
        }
    }

    // ---- epilogue: AO fp16, K-pair-interleaved columns ----
    float inv0 = 1.f / lrow0;
    float inv1 = 1.f / lrow1;
    int qrow = q0 + wrow + gid;
    __half* O0 = Og + (size_t)(b * S_ + qrow) * E_ + h * D_;
    __half* O1 = O0 + 8 * (size_t)E_;
#pragma unroll
    for (int nt = 0; nt < 16; ++nt) {
        int np = 2 * tig + (nt & 1);
        int off = (nt >> 1) * 16 + np * 2;
        *(__half2*)(O0 + off) = __floats2half2_rn(accO[nt][0] * inv0, accO[nt][1] * inv0);
        *(__half2*)(O1 + off) = __floats2half2_rn(accO[nt][2] * inv1, accO[nt][3] * inv1);
    }
}

// ============================================================================
// kernel_launch
// ============================================================================
extern "C" void kernel_launch(void* const* d_in, const int* in_sizes, int n_in,
                              void* d_out, int out_size)
{
    const float* x    = (const float*)d_in[0];
    const float* Wqkv = (const float*)d_in[1];
    const float* Wo   = (const float*)d_in[2];
    const float* fc   = (const float*)d_in[3];
    float* out = (float*)d_out;

    __half *xh, *wqkvT, *woT, *Q, *K, *V, *AO;
    cudaGetSymbolAddress((void**)&xh, g_xh);
    cudaGetSymbolAddress((void**)&wqkvT, g_wqkvT);
    cudaGetSymbolAddress((void**)&woT, g_woT);
    cudaGetSymbolAddress((void**)&Q, g_qh);
    cudaGetSymbolAddress((void**)&K, g_kh);
    cudaGetSymbolAddress((void**)&V, g_vh);
    cudaGetSymbolAddress((void**)&AO, g_aoh);

    cudaFuncSetAttribute(gemm_mma, cudaFuncAttributeMaxDynamicSharedMemorySize, GEMM_SMEM);
    cudaFuncSetAttribute(flash_mma, cudaFuncAttributeMaxDynamicSharedMemorySize, FL_SMEM);

    round_copy_h<<<(B_ * S_ * E_) / 16 / 256, 256>>>(x, xh);
    {
        dim3 g(E3_ / 32, E_ / 32);
        transpose_round_h<<<g, 256>>>(Wqkv, wqkvT, E_, E3_);
    }
    {
        dim3 g(E_ / 32, E_ / 32);
        transpose_round_h<<<g, 256>>>(Wo, woT, E_, E_);
    }

    // 1) QKV GEMM with fused RoPE+scatter epilogue
    {
        dim3 grid(E3_ / 128, (B_ * S_) / 128);
        gemm_mma<<<grid, 256, GEMM_SMEM>>>(xh, wqkvT, nullptr, fc, Q, K, V,
                                           B_ * S_, E3_, E_, 1);
    }
    // 2) flash attention (BM=128, BN=64, 2 CTAs/SM)
    {
        dim3 grid(S_ / 128, H_, B_);
        flash_mma<<<grid, 256, FL_SMEM>>>(Q, K, V, AO);
    }
    // 3) out = AO @ woT^T
    {
        dim3 grid(E_ / 128, (B_ * S_) / 128);
        gemm_mma<<<grid, 256, GEMM_SMEM>>>(AO, woT, out, nullptr, nullptr, nullptr,
                                           nullptr, B_ * S_, E_, E_, 0);
    }
}

// round 13
// speedup vs baseline: 1.1852x; 1.1852x over previous
#include <cuda_runtime.h>
#include <cuda_fp16.h>
#include <cstdint>
#include <math.h>

#define B_  2
#define S_  2048
#define E_  2048
#define H_  16
#define D_  128
#define E3_ 6144

// ---------------- scratch ----------------
__device__ __half g_xh [B_ * S_ * E_];       // x, fp16, K-pair-interleaved
__device__ __half g_wqkvT[E3_ * E_];         // Wqkv^T fp16 interleaved
__device__ __half g_woT [E_ * E_];           // Wo^T fp16 interleaved
__device__ __half g_qh[B_ * H_ * S_ * D_];   // Q fp16 d-interleaved, scaled
__device__ __half g_kh[B_ * H_ * S_ * D_];   // K fp16 d-interleaved
__device__ __half g_vh[B_ * H_ * S_ * D_];   // V fp16 natural
__device__ __half g_aoh[B_ * S_ * E_];       // attn out fp16 interleaved

// ---------------- helpers ----------------
__device__ __forceinline__ uint32_t smem_u32(const void* p) {
    uint32_t a;
    asm("{ .reg .u64 t; cvta.to.shared.u64 t, %1; cvt.u32.u64 %0, t; }" : "=r"(a) : "l"(p));
    return a;
}

#define CP_ASYNC16(sa, gp) \
    asm volatile("cp.async.cg.shared.global [%0], [%1], 16;" :: "r"(sa), "l"(gp))
#define CP_COMMIT() asm volatile("cp.async.commit_group;" ::: "memory")
#define CP_WAIT1()  asm volatile("cp.async.wait_group 1;" ::: "memory")
#define CP_WAIT0()  asm volatile("cp.async.wait_group 0;" ::: "memory")

__device__ __forceinline__ void mma_f16_16n8k16(
    float& c0, float& c1, float& c2, float& c3,
    uint32_t a0, uint32_t a1, uint32_t a2, uint32_t a3,
    uint32_t b0, uint32_t b1)
{
    asm volatile(
        "mma.sync.aligned.m16n8k16.row.col.f32.f16.f16.f32 "
        "{%0,%1,%2,%3}, {%4,%5,%6,%7}, {%8,%9}, {%0,%1,%2,%3};"
        : "+f"(c0), "+f"(c1), "+f"(c2), "+f"(c3)
        : "r"(a0), "r"(a1), "r"(a2), "r"(a3), "r"(b0), "r"(b1));
}

__device__ __forceinline__ uint32_t pack_h2(float a, float b) {
    __half2 t = __floats2half2_rn(a, b);
    return *(uint32_t*)&t;
}

// pair-interleave position within each 16-half block
__device__ __forceinline__ int ilv16(int t) {
    int p = (t >> 1) & 7;
    int np = ((p & 3) << 1) | ((p >> 2) & 1);
    return (t & ~15) | (np << 1) | (t & 1);
}

// ============================================================================
// fp16 mma.sync GEMM with fused epilogue (validated R10, unchanged).
// ============================================================================
#define GSZ 8192
#define GEMM_SMEM (3 * 2 * GSZ * 2)

__global__ __launch_bounds__(256, 2) void gemm_mma(
    const __half* __restrict__ A, const __half* __restrict__ Bt,
    float* __restrict__ C, const float* __restrict__ fc,
    __half* __restrict__ Qo, __half* __restrict__ Ko, __half* __restrict__ Vo,
    int M, int Ntot, int K, int mode)
{
    extern __shared__ __half smh[];
    const int tid  = threadIdx.x;
    const int wid  = tid >> 5;
    const int lane = tid & 31;
    const int gid  = lane >> 2;
    const int tig  = lane & 3;
    const int wm   = wid & 1;
    const int wn   = wid >> 1;
    const int m0 = blockIdx.y * 128;
    const int n0 = blockIdx.x * 128;

    const int r_ld = tid >> 3;
    const int c_ld = tid & 7;
    const int c_sw = c_ld ^ ((r_ld & 3) << 1);
    const int x = (gid & 3) << 1;

    float c[4][4][4];
#pragma unroll
    for (int i = 0; i < 4; ++i)
#pragma unroll
        for (int j = 0; j < 4; ++j)
#pragma unroll
            for (int t = 0; t < 4; ++t) c[i][j][t] = 0.f;

    auto load_stage = [&](int kc, int slot) {
        __half* As = smh + slot * 2 * GSZ;
        __half* Bs = As + GSZ;
        const __half* Ag = A + (size_t)m0 * K + kc * 64;
        const __half* Bg = Bt + (size_t)n0 * K + kc * 64;
#pragma unroll
        for (int j = 0; j < 4; ++j) {
            int r = r_ld + j * 32;
            CP_ASYNC16(smem_u32(As + r * 64 + c_sw * 8), Ag + (size_t)r * K + c_ld * 8);
        }
#pragma unroll
        for (int j = 0; j < 4; ++j) {
            int r = r_ld + j * 32;
            CP_ASYNC16(smem_u32(Bs + r * 64 + c_sw * 8), Bg + (size_t)r * K + c_ld * 8);
        }
    };

    const int nk = K >> 6;
    load_stage(0, 0); CP_COMMIT();
    load_stage(1, 1); CP_COMMIT();

    for (int kc = 0; kc < nk; ++kc) {
        CP_WAIT1();
        __syncthreads();
        if (kc + 2 < nk) { load_stage(kc + 2, (kc + 2) % 3); CP_COMMIT(); }

        const __half* As = smh + (kc % 3) * 2 * GSZ;
        const __half* Bs = As + GSZ;
        const __half* Aw = As + (wm * 64 + gid) * 64;
        const __half* Bw = Bs + (wn * 32 + gid) * 64;

#pragma unroll
        for (int ks = 0; ks < 4; ++ks) {
            const int swc = (2 * ks + (tig >> 1)) ^ x;
            const int off = swc * 8 + (tig & 1) * 4;
            uint32_t a[4][4], b[4][2];
#pragma unroll
            for (int mt = 0; mt < 4; ++mt) {
                uint2 p0 = *(const uint2*)(Aw + mt * 1024 + off);
                uint2 p1 = *(const uint2*)(Aw + mt * 1024 + 512 + off);
                a[mt][0] = p0.x;  a[mt][2] = p0.y;
                a[mt][1] = p1.x;  a[mt][3] = p1.y;
            }
#pragma unroll
            for (int nt = 0; nt < 4; ++nt) {
                uint2 pb = *(const uint2*)(Bw + nt * 512 + off);
                b[nt][0] = pb.x;  b[nt][1] = pb.y;
            }
#pragma unroll
            for (int mt = 0; mt < 4; ++mt)
#pragma unroll
                for (int nt = 0; nt < 4; ++nt)
                    mma_f16_16n8k16(c[mt][nt][0], c[mt][nt][1], c[mt][nt][2], c[mt][nt][3],
                                    a[mt][0], a[mt][1], a[mt][2], a[mt][3],
                                    b[nt][0], b[nt][1]);
        }
    }

    if (mode == 0) {
#pragma unroll
        for (int mt = 0; mt < 4; ++mt) {
            int r0 = m0 + wm * 64 + mt * 16 + gid;
#pragma unroll
            for (int nt = 0; nt < 4; ++nt) {
                int col = n0 + wn * 32 + nt * 8 + 2 * tig;
                *(float2*)(C + (size_t)r0 * Ntot + col) = make_float2(c[mt][nt][0], c[mt][nt][1]);
                *(float2*)(C + (size_t)(r0 + 8) * Ntot + col) = make_float2(c[mt][nt][2], c[mt][nt][3]);
            }
        }
    } else {
        const int region = n0 >> 11;
        const int h = (n0 & 2047) >> 7;
        const float sc = 0.08838834764831845f;
#pragma unroll
        for (int mt = 0; mt < 4; ++mt) {
            int r0 = m0 + wm * 64 + mt * 16 + gid;
#pragma unroll
            for (int half_row = 0; half_row < 2; ++half_row) {
                int row = r0 + half_row * 8;
                int s = row & 2047, b = row >> 11;
                size_t bo = ((size_t)(b * H_ + h) * S_ + s) * (size_t)D_;
#pragma unroll
                for (int nt = 0; nt < 4; ++nt) {
                    float v0 = c[mt][nt][half_row * 2 + 0];
                    float v1 = c[mt][nt][half_row * 2 + 1];
                    int i = wn * 16 + nt * 4 + tig;
                    if (region < 2) {
                        float co = fc[s * 128 + 2 * i];
                        float sn = fc[s * 128 + 2 * i + 1];
                        float re = v0 * co - v1 * sn;
                        float im = v1 * co + v0 * sn;
                        if (region == 0) { re *= sc; im *= sc; }
                        int p = i & 7;
                        int np = ((p & 3) << 1) | ((p >> 2) & 1);
                        int pos = (i >> 3) * 16 + np * 2;
                        __half2 hv = __floats2half2_rn(re, im);
                        if (region == 0) *(__half2*)(Qo + bo + pos) = hv;
                        else             *(__half2*)(Ko + bo + pos) = hv;
                    } else {
                        *(__half2*)(Vo + bo + 2 * i) = __floats2half2_rn(v0, v1);
                    }
                }
            }
        }
    }
}

// ============================================================================
// prep kernels (validated)
// ============================================================================
__global__ __launch_bounds__(256) void round_copy_h(const float* __restrict__ in,
                                                    __half* __restrict__ out) {
    int i = blockIdx.x * 256 + threadIdx.x;
    const float* p = in + 16 * i;
    __half2 h[8];
#pragma unroll
    for (int j = 0; j < 8; ++j) {
        int pp = (j >> 1) | ((j & 1) << 2);
        h[j] = __floats2half2_rn(p[2 * pp], p[2 * pp + 1]);
    }
    uint4* q = (uint4*)(out + 16 * i);
    q[0] = *(uint4*)(h);
    q[1] = *(uint4*)(h + 4);
}

__global__ __launch_bounds__(256) void transpose_round_h(
    const float* __restrict__ W, __half* __restrict__ Wt, int K, int N)
{
    __shared__ float t[32][33];
    int n0 = blockIdx.x * 32, k0 = blockIdx.y * 32;
    int tx = threadIdx.x & 31, ty = threadIdx.x >> 5;
#pragma unroll
    for (int j = 0; j < 4; ++j)
        t[ty + j * 8][tx] = W[(size_t)(k0 + ty + j * 8) * N + n0 + tx];
    __syncthreads();
    int ktx = ilv16(tx);
#pragma unroll
    for (int j = 0; j < 4; ++j)
        Wt[(size_t)(n0 + ty + j * 8) * K + k0 + ktx] = __float2half(t[tx][ty + j * 8]);
}

// ============================================================================
// Flash attention v4: R10 shape (BM=128, BN=64, 256 threads, Q in registers,
// 1 CTA/SM) + FA2 register-P (sacc C-fragment == PV A-fragment; no P smem,
// ONE barrier per iter) + natural-order V in smem (PV B via 2x LDS.32,
// conflict-free) + formally-correct cp.async ordering:
//   top: commit K(kt+1); wait_group 1  => K(cur) AND V(cur) complete; barrier.
//   mid: commit V(kt+1) (no wait — completes before next top wait).
// ============================================================================
#define KSP 136
#define VSP 72
#define KS_H (64 * KSP)
#define VTS_H (128 * VSP)
#define FL_SMEM ((2 * KS_H + 2 * VTS_H) * 2)   // 71680 B

__global__ __launch_bounds__(256, 1) void flash_mma(
    const __half* __restrict__ Qg, const __half* __restrict__ Kg,
    const __half* __restrict__ Vg, __half* __restrict__ Og)
{
    extern __shared__ __half smh[];
    __half* Ks  = smh;                 // [2][64][KSP]   (d-interleaved cols)
    __half* Vts = smh + 2 * KS_H;      // [2][128(d)][VSP(key, natural)]

    const int tid  = threadIdx.x;
    const int wid  = tid >> 5;
    const int lane = tid & 31;
    const int gid  = lane >> 2;
    const int tig  = lane & 3;
    const int b = blockIdx.z, h = blockIdx.y;
    const int qt = (int)gridDim.x - 1 - (int)blockIdx.x;  // big tiles first
    const int q0 = qt * 128;
    const int wrow = wid * 16;
    const size_t base = (size_t)(b * H_ + h) * S_ * D_;

    // ---- Q fragments, persistent in registers ----
    uint2 aq[8][2];
    {
        const __half* Qp0 = Qg + base + (size_t)(q0 + wrow + gid) * D_ + tig * 4;
        const __half* Qp1 = Qp0 + 8 * D_;
#pragma unroll
        for (int ks = 0; ks < 8; ++ks) {
            aq[ks][0] = *(const uint2*)(Qp0 + ks * 16);
            aq[ks][1] = *(const uint2*)(Qp1 + ks * 16);
        }
    }

    float accO[16][4];
#pragma unroll
    for (int nt = 0; nt < 16; ++nt)
#pragma unroll
        for (int t = 0; t < 4; ++t) accO[nt][t] = 0.f;
    float mrow0 = -3.0e38f, mrow1 = -3.0e38f;
    float lrow0 = 0.f, lrow1 = 0.f;

    auto load_K = [&](int kt, int bf) {
        const __half* Kgp = Kg + base + (size_t)kt * 64 * D_;
        __half* dst = Ks + bf * KS_H;
#pragma unroll
        for (int j = 0; j < 4; ++j) {
            int q = tid + j * 256;
            int r = q >> 4, cc = q & 15;
            CP_ASYNC16(smem_u32(dst + r * KSP + cc * 8), Kgp + (size_t)r * D_ + cc * 8);
        }
    };
    auto load_V = [&](int kt, int bf) {       // transpose, NATURAL key order
        const __half* Vgp = Vg + base + (size_t)kt * 64 * D_;
        __half* dst = Vts + bf * VTS_H;
#pragma unroll
        for (int j = 0; j < 8; ++j) {
            int e = tid + j * 256;
            int key = e & 63, d4 = e >> 6;
            uint2 v4 = *(const uint2*)(Vgp + (size_t)key * D_ + d4 * 4);
            __half2 lo = *(__half2*)&v4.x;
            __half2 hi = *(__half2*)&v4.y;
            dst[(d4 * 4 + 0) * VSP + key] = __low2half(lo);
            dst[(d4 * 4 + 1) * VSP + key] = __high2half(lo);
            dst[(d4 * 4 + 2) * VSP + key] = __low2half(hi);
            dst[(d4 * 4 + 3) * VSP + key] = __high2half(hi);
        }
    };

    const int nkt = 2 * qt + 1;
    load_K(0, 0); CP_COMMIT();
    load_V(0, 0); CP_COMMIT();

    for (int kt = 0; kt <= nkt; ++kt) {
        const int cur = kt & 1, nxt = cur ^ 1;
        if (kt < nkt) { load_K(kt + 1, nxt); CP_COMMIT(); CP_WAIT1(); }
        else          { CP_WAIT0(); }
        __syncthreads();   // K[cur] AND V[cur] complete in all threads, visible

        // ---- S = Q @ K^T ----
        float sacc[8][4];
#pragma unroll
        for (int nt = 0; nt < 8; ++nt)
#pragma unroll
            for (int t = 0; t < 4; ++t) sacc[nt][t] = 0.f;

        const __half* Kb = Ks + cur * KS_H + gid * KSP + tig * 4;
#pragma unroll
        for (int ks = 0; ks < 8; ++ks) {
#pragma unroll
            for (int nt = 0; nt < 8; ++nt) {
                uint2 bb = *(const uint2*)(Kb + nt * 8 * KSP + ks * 16);
                mma_f16_16n8k16(sacc[nt][0], sacc[nt][1], sacc[nt][2], sacc[nt][3],
                                aq[ks][0].x, aq[ks][1].x, aq[ks][0].y, aq[ks][1].y,
                                bb.x, bb.y);
            }
        }

        if (kt < nkt) { load_V(kt + 1, nxt); CP_COMMIT(); }

        // ---- causal mask ----
        const int k0 = kt * 64;
        if (k0 + 63 > q0 + wrow) {
            int r0 = q0 + wrow + gid, r1 = r0 + 8;
#pragma unroll
            for (int nt = 0; nt < 8; ++nt) {
                int cA = k0 + nt * 8 + 2 * tig, cB = cA + 1;
                if (cA > r0) sacc[nt][0] = -1.0e30f;
                if (cB > r0) sacc[nt][1] = -1.0e30f;
                if (cA > r1) sacc[nt][2] = -1.0e30f;
                if (cB > r1) sacc[nt][3] = -1.0e30f;
            }
        }

        // ---- online softmax (2 rows/thread, 4-lane groups) ----
        float mx0 = -3.0e38f, mx1 = -3.0e38f;
#pragma unroll
        for (int nt = 0; nt < 8; ++nt) {
            mx0 = fmaxf(mx0, fmaxf(sacc[nt][0], sacc[nt][1]));
            mx1 = fmaxf(mx1, fmaxf(sacc[nt][2], sacc[nt][3]));
        }
        mx0 = fmaxf(mx0, __shfl_xor_sync(0xffffffffu, mx0, 1));
        mx0 = fmaxf(mx0, __shfl_xor_sync(0xffffffffu, mx0, 2));
        mx1 = fmaxf(mx1, __shfl_xor_sync(0xffffffffu, mx1, 1));
        mx1 = fmaxf(mx1, __shfl_xor_sync(0xffffffffu, mx1, 2));

        float mn0 = fmaxf(mrow0, mx0);
        float mn1 = fmaxf(mrow1, mx1);
        float al0 = __expf(mrow0 - mn0);
        float al1 = __expf(mrow1 - mn1);
        mrow0 = mn0; mrow1 = mn1;

        float s0 = 0.f, s1 = 0.f;
#pragma unroll
        for (int nt = 0; nt < 8; ++nt) {
            sacc[nt][0] = __expf(sacc[nt][0] - mn0);
            sacc[nt][1] = __expf(sacc[nt][1] - mn0);
            sacc[nt][2] = __expf(sacc[nt][2] - mn1);
            sacc[nt][3] = __expf(sacc[nt][3] - mn1);
            s0 += sacc[nt][0] + sacc[nt][1];
            s1 += sacc[nt][2] + sacc[nt][3];
        }
        s0 += __shfl_xor_sync(0xffffffffu, s0, 1);
        s0 += __shfl_xor_sync(0xffffffffu, s0, 2);
        s1 += __shfl_xor_sync(0xffffffffu, s1, 1);
        s1 += __shfl_xor_sync(0xffffffffu, s1, 2);
        lrow0 = lrow0 * al0 + s0;
        lrow1 = lrow1 * al1 + s1;

#pragma unroll
        for (int nt = 0; nt < 16; ++nt) {
            accO[nt][0] *= al0; accO[nt][1] *= al0;
            accO[nt][2] *= al1; accO[nt][3] *= al1;
        }

        // ---- O += P @ V : P directly from sacc (FA2 register fragments) ----
        const __half* Vb = Vts + cur * VTS_H + gid * VSP + 2 * tig;
#pragma unroll
        for (int m = 0; m < 4; ++m) {
            uint32_t pa0 = pack_h2(sacc[2 * m][0],     sacc[2 * m][1]);
            uint32_t pa1 = pack_h2(sacc[2 * m][2],     sacc[2 * m][3]);
            uint32_t pa2 = pack_h2(sacc[2 * m + 1][0], sacc[2 * m + 1][1]);
            uint32_t pa3 = pack_h2(sacc[2 * m + 1][2], sacc[2 * m + 1][3]);
#pragma unroll
            for (int nt = 0; nt < 16; ++nt) {
                const __half* vp = Vb + nt * 8 * VSP + m * 16;
                uint32_t b0 = *(const uint32_t*)(vp);
                uint32_t b1 = *(const uint32_t*)(vp + 8);
                mma_f16_16n8k16(accO[nt][0], accO[nt][1], accO[nt][2], accO[nt][3],
                                pa0, pa1, pa2, pa3, b0, b1);
            }
        }
    }

    // ---- epilogue: AO fp16, K-pair-interleaved columns ----
    float inv0 = 1.f / lrow0;
    float inv1 = 1.f / lrow1;
    int qrow = q0 + wrow + gid;
    __half* O0 = Og + (size_t)(b * S_ + qrow) * E_ + h * D_;
    __half* O1 = O0 + 8 * (size_t)E_;
#pragma unroll
    for (int nt = 0; nt < 16; ++nt) {
        int np = 2 * tig + (nt & 1);
        int off = (nt >> 1) * 16 + np * 2;
        *(__half2*)(O0 + off) = __floats2half2_rn(accO[nt][0] * inv0, accO[nt][1] * inv0);
        *(__half2*)(O1 + off) = __floats2half2_rn(accO[nt][2] * inv1, accO[nt][3] * inv1);
    }
}

// ============================================================================
// kernel_launch
// ============================================================================
extern "C" void kernel_launch(void* const* d_in, const int* in_sizes, int n_in,
                              void* d_out, int out_size)
{
    const float* x    = (const float*)d_in[0];
    const float* Wqkv = (const float*)d_in[1];
    const float* Wo   = (const float*)d_in[2];
    const float* fc   = (const float*)d_in[3];
    float* out = (float*)d_out;

    __half *xh, *wqkvT, *woT, *Q, *K, *V, *AO;
    cudaGetSymbolAddress((void**)&xh, g_xh);
    cudaGetSymbolAddress((void**)&wqkvT, g_wqkvT);
    cudaGetSymbolAddress((void**)&woT, g_woT);
    cudaGetSymbolAddress((void**)&Q, g_qh);
    cudaGetSymbolAddress((void**)&K, g_kh);
    cudaGetSymbolAddress((void**)&V, g_vh);
    cudaGetSymbolAddress((void**)&AO, g_aoh);

    cudaFuncSetAttribute(gemm_mma, cudaFuncAttributeMaxDynamicSharedMemorySize, GEMM_SMEM);
    cudaFuncSetAttribute(flash_mma, cudaFuncAttributeMaxDynamicSharedMemorySize, FL_SMEM);

    round_copy_h<<<(B_ * S_ * E_) / 16 / 256, 256>>>(x, xh);
    {
        dim3 g(E3_ / 32, E_ / 32);
        transpose_round_h<<<g, 256>>>(Wqkv, wqkvT, E_, E3_);
    }
    {
        dim3 g(E_ / 32, E_ / 32);
        transpose_round_h<<<g, 256>>>(Wo, woT, E_, E_);
    }

    // 1) QKV GEMM with fused RoPE+scatter epilogue
    {
        dim3 grid(E3_ / 128, (B_ * S_) / 128);
        gemm_mma<<<grid, 256, GEMM_SMEM>>>(xh, wqkvT, nullptr, fc, Q, K, V,
                                           B_ * S_, E3_, E_, 1);
    }
    // 2) flash attention (register-P, one barrier per key tile)
    {
        dim3 grid(S_ / 128, H_, B_);
        flash_mma<<<grid, 256, FL_SMEM>>>(Q, K, V, AO);
    }
    // 3) out = AO @ woT^T
    {
        dim3 grid(E_ / 128, (B_ * S_) / 128);
        gemm_mma<<<grid, 256, GEMM_SMEM>>>(AO, woT, out, nullptr, nullptr, nullptr,
                                           nullptr, B_ * S_, E_, E_, 0);
    }
}